// round 4
// baseline (speedup 1.0000x reference)
#include <cuda_runtime.h>
#include <cuda_bf16.h>
#include <cstdint>

// Problem dims
#define BATCH    8192
#define DIM      128          // in_dim == out_dim
#define KTOT     384          // 3 powers * 128 inputs
#define KC       64           // K per chunk
#define NCHUNK   6
#define MTILE    64           // batch rows per CTA
#define THREADS  256          // 8 warps: 2 (m) x 4 (n)
#define NCTA     (BATCH / MTILE)   // 128

// Chunk order: c = half*3 + pw  (half = j>=64, pw = degree-1)
// Pre-split coefficients in PERMUTED K order: g_B*[o*384 + c*64 + (j&63)]
__device__ __nv_bfloat16 g_Bh[DIM * KTOT];
__device__ __nv_bfloat16 g_Bl[DIM * KTOT];
__device__ float g_Bias[DIM];

// smem buffer layout (per buffer):
//   Ah [64][64]bf16 @ 0      (8 KB)
//   Al [64][64]bf16 @ 8192   (8 KB)
//   Bh [128][64]bf16 @ 16384 (16 KB)
//   Bl [128][64]bf16 @ 32768 (16 KB)
#define REG_AL 8192u
#define REG_BH 16384u
#define REG_BL 32768u
#define BUF_STRIDE 49152u
#define SMEM_TOTAL (2 * BUF_STRIDE)

// ---------------- helpers ----------------
__device__ __forceinline__ uint32_t smem_u32(const void* p) {
    uint32_t a;
    asm("{ .reg .u64 t; cvta.to.shared.u64 t, %1; cvt.u32.u64 %0, t; }" : "=r"(a) : "l"(p));
    return a;
}
__device__ __forceinline__ uint32_t swz128(uint32_t off) { return off ^ ((off >> 3) & 0x70); }

#define CP_ASYNC16(dst_u32, src_ptr)                                              \
    asm volatile("{ .reg .u64 g; cvta.to.global.u64 g, %1;\n"                     \
                 "cp.async.cg.shared.global [%0], [g], 16; }"                     \
                 :: "r"(dst_u32), "l"(src_ptr) : "memory")
#define CP_COMMIT() asm volatile("cp.async.commit_group;" ::: "memory")
#define CP_WAIT0()  asm volatile("cp.async.wait_group 0;" ::: "memory")

#define LDSM4(r, addr)                                                            \
    asm volatile("ldmatrix.sync.aligned.m8n8.x4.shared.b16 {%0,%1,%2,%3}, [%4];"  \
                 : "=r"((r)[0]), "=r"((r)[1]), "=r"((r)[2]), "=r"((r)[3])         \
                 : "r"(addr))

#define MMA_BF16(c, A, b0v, b1v)                                                  \
    asm volatile("mma.sync.aligned.m16n8k16.row.col.f32.bf16.bf16.f32 "           \
                 "{%0,%1,%2,%3}, {%4,%5,%6,%7}, {%8,%9}, {%0,%1,%2,%3};"          \
                 : "+f"((c)[0]), "+f"((c)[1]), "+f"((c)[2]), "+f"((c)[3])         \
                 : "r"((A)[0]), "r"((A)[1]), "r"((A)[2]), "r"((A)[3]),            \
                   "r"(b0v), "r"(b1v))

__device__ __forceinline__ uint32_t split_pack2(float a, float b, uint32_t& lo_pack) {
    __nv_bfloat16 ha = __float2bfloat16(a), hb = __float2bfloat16(b);
    __nv_bfloat16 la = __float2bfloat16(a - __bfloat162float(ha));
    __nv_bfloat16 lb = __float2bfloat16(b - __bfloat162float(hb));
    lo_pack = (uint32_t)__bfloat16_as_ushort(la) | ((uint32_t)__bfloat16_as_ushort(lb) << 16);
    return (uint32_t)__bfloat16_as_ushort(ha) | ((uint32_t)__bfloat16_as_ushort(hb) << 16);
}

// ---------------- prologue: split coeff (permuted K) + fused bias ----------------
__global__ void prep_kernel(const float* __restrict__ coeff) {
    const int tid = threadIdx.x;
    const int idx = blockIdx.x * 256 + tid;       // edge index [0, 16384)
    const int o = idx >> 7, j = idx & 127;
    float4 cf = reinterpret_cast<const float4*>(coeff)[idx];
    float v[3] = {cf.y, cf.z, cf.w};              // degrees 1..3
    const int cbase = (j >= 64) ? 3 : 0;
#pragma unroll
    for (int pw = 0; pw < 3; ++pw) {
        float w = v[pw];
        __nv_bfloat16 h = __float2bfloat16(w);
        __nv_bfloat16 l = __float2bfloat16(w - __bfloat162float(h));
        int off = o * KTOT + (cbase + pw) * 64 + (j & 63);
        g_Bh[off] = h;
        g_Bl[off] = l;
    }
    // bias = sum over j of degree-0 coeff, 128 threads per o
    float s = cf.x;
#pragma unroll
    for (int off = 16; off; off >>= 1)
        s += __shfl_xor_sync(0xffffffffu, s, off);
    __shared__ float ps[8];
    if ((tid & 31) == 0) ps[tid >> 5] = s;
    __syncthreads();
    if (tid == 0)   g_Bias[o] = ps[0] + ps[1] + ps[2] + ps[3];
    if (tid == 128) g_Bias[o] = ps[4] + ps[5] + ps[6] + ps[7];
}

// ---------------- main kernel ----------------
__global__ void __launch_bounds__(THREADS, 1)
kan_mma(const float* __restrict__ x, float* __restrict__ out) {
    extern __shared__ char smem[];
    const uint32_t sb = smem_u32(smem);
    const int tid  = threadIdx.x;
    const int lane = tid & 31;
    const int wid  = tid >> 5;
    const int b0   = blockIdx.x * MTILE;

    // staging thread map: row sr (0..63), quarter sq (0..3) -> 16 consecutive j
    const int sr = tid >> 2;
    const int sq = tid & 3;

    // warp tile coords (32 x 32)
    const int m0 = (wid & 1) * 32;
    const int n0 = (wid >> 1) * 32;

    float acc[2][4][4];
#pragma unroll
    for (int mi = 0; mi < 2; ++mi)
#pragma unroll
        for (int nj = 0; nj < 4; ++nj)
#pragma unroll
            for (int i = 0; i < 4; ++i) acc[mi][nj][i] = 0.f;

    float4 xv[4];     // current j-half of x, persists across 3 chunks
    float  w[16];     // running power x^(pw+1)

    // ---- staging helpers ----
    auto issue_B = [&](int cn, uint32_t tb) {
#pragma unroll
        for (int i = 0; i < 4; ++i) {
            int idx = tid + i * THREADS;          // 0..1023
            int n = idx >> 3, k8 = idx & 7;
            const __nv_bfloat16* srcH = g_Bh + n * KTOT + cn * KC + k8 * 8;
            const __nv_bfloat16* srcL = g_Bl + n * KTOT + cn * KC + k8 * 8;
            uint32_t sw = swz128((uint32_t)(n * 128 + k8 * 16));
            CP_ASYNC16(sb + tb + REG_BH + sw, srcH);
            CP_ASYNC16(sb + tb + REG_BL + sw, srcL);
        }
    };
    auto issue_X = [&](int cn) {                  // only for cn % 3 == 0
        const int jhalf = (cn / 3) * 64;
        const float4* xs = reinterpret_cast<const float4*>(
            x + (size_t)(b0 + sr) * DIM + jhalf);
#pragma unroll
        for (int i = 0; i < 4; ++i) xv[i] = xs[sq * 4 + i];
    };
    auto store_A = [&](int cn, uint32_t tb) {
        if (cn % 3 == 0) {
#pragma unroll
            for (int i = 0; i < 4; ++i) {
                w[4 * i + 0] = xv[i].x; w[4 * i + 1] = xv[i].y;
                w[4 * i + 2] = xv[i].z; w[4 * i + 3] = xv[i].w;
            }
        } else {
#pragma unroll
            for (int i = 0; i < 4; ++i) {
                w[4 * i + 0] *= xv[i].x; w[4 * i + 1] *= xv[i].y;
                w[4 * i + 2] *= xv[i].z; w[4 * i + 3] *= xv[i].w;
            }
        }
        uint32_t hp[8], lp[8];
#pragma unroll
        for (int i = 0; i < 8; ++i) hp[i] = split_pack2(w[2 * i], w[2 * i + 1], lp[i]);
        uint32_t base = (uint32_t)(sr * 128 + sq * 32);
        *reinterpret_cast<uint4*>(smem + tb + swz128(base)) =
            make_uint4(hp[0], hp[1], hp[2], hp[3]);
        *reinterpret_cast<uint4*>(smem + tb + swz128(base + 16)) =
            make_uint4(hp[4], hp[5], hp[6], hp[7]);
        *reinterpret_cast<uint4*>(smem + tb + REG_AL + swz128(base)) =
            make_uint4(lp[0], lp[1], lp[2], lp[3]);
        *reinterpret_cast<uint4*>(smem + tb + REG_AL + swz128(base + 16)) =
            make_uint4(lp[4], lp[5], lp[6], lp[7]);
    };

    // ---- prologue: stage chunk 0 ----
    issue_B(0, 0);
    CP_COMMIT();
    issue_X(0);
    store_A(0, 0);
    CP_WAIT0();
    __syncthreads();

    // per-lane ldmatrix base coords
    const uint32_t a_row = (uint32_t)(m0 + (lane & 15));
    const uint32_t a_kb  = (uint32_t)((lane >> 4) * 16);
    const uint32_t b_row = (uint32_t)(n0 + (lane & 7) + ((lane >> 4) << 3));
    const uint32_t b_kb  = (uint32_t)(((lane >> 3) & 1) * 16);

    auto load_frags = [&](uint32_t tb, int ks, uint32_t ah[2][4], uint32_t al[2][4],
                          uint32_t bh[2][4], uint32_t bl[2][4]) {
#pragma unroll
        for (int mi = 0; mi < 2; ++mi) {
            uint32_t off = (a_row + mi * 16) * 128 + ks * 32 + a_kb;
            LDSM4(ah[mi], sb + tb + swz128(off));
            LDSM4(al[mi], sb + tb + REG_AL + swz128(off));
        }
#pragma unroll
        for (int ni = 0; ni < 2; ++ni) {
            uint32_t off = (b_row + ni * 16) * 128 + ks * 32 + b_kb;
            LDSM4(bh[ni], sb + tb + REG_BH + swz128(off));
            LDSM4(bl[ni], sb + tb + REG_BL + swz128(off));
        }
    };
    // term-major: 8 independent accs between touches of the same acc
    auto mma_all = [&](uint32_t ah[2][4], uint32_t al[2][4],
                       uint32_t bh[2][4], uint32_t bl[2][4]) {
#pragma unroll
        for (int mi = 0; mi < 2; ++mi)
#pragma unroll
            for (int nj = 0; nj < 4; ++nj) {
                const int ni = nj >> 1, br = (nj & 1) * 2;
                MMA_BF16(acc[mi][nj], ah[mi], bh[ni][br], bh[ni][br + 1]);
            }
#pragma unroll
        for (int mi = 0; mi < 2; ++mi)
#pragma unroll
            for (int nj = 0; nj < 4; ++nj) {
                const int ni = nj >> 1, br = (nj & 1) * 2;
                MMA_BF16(acc[mi][nj], al[mi], bh[ni][br], bh[ni][br + 1]);
            }
#pragma unroll
        for (int mi = 0; mi < 2; ++mi)
#pragma unroll
            for (int nj = 0; nj < 4; ++nj) {
                const int ni = nj >> 1, br = (nj & 1) * 2;
                MMA_BF16(acc[mi][nj], ah[mi], bl[ni][br], bl[ni][br + 1]);
            }
    };

    for (int c = 0; c < NCHUNK; ++c) {
        const uint32_t tb  = (uint32_t)(c & 1) * BUF_STRIDE;
        const uint32_t tbn = (uint32_t)((c + 1) & 1) * BUF_STRIDE;

        if (c + 1 < NCHUNK) {
            issue_B(c + 1, tbn);
            CP_COMMIT();
            if ((c + 1) % 3 == 0) issue_X(c + 1);
        }

        // ---- fragment-pipelined MMA over 4 k16-steps ----
        {
            uint32_t ah0[2][4], al0[2][4], bh0[2][4], bl0[2][4];
            uint32_t ah1[2][4], al1[2][4], bh1[2][4], bl1[2][4];
            load_frags(tb, 0, ah0, al0, bh0, bl0);
            load_frags(tb, 1, ah1, al1, bh1, bl1);
            mma_all(ah0, al0, bh0, bl0);
            load_frags(tb, 2, ah0, al0, bh0, bl0);
            mma_all(ah1, al1, bh1, bl1);
            load_frags(tb, 3, ah1, al1, bh1, bl1);
            mma_all(ah0, al0, bh0, bl0);
            mma_all(ah1, al1, bh1, bl1);
        }

        if (c + 1 < NCHUNK) {
            store_A(c + 1, tbn);
            CP_WAIT0();
        }
        __syncthreads();
    }

    // ---- epilogue: bias + store ----
    float2 bs[4];
#pragma unroll
    for (int nj = 0; nj < 4; ++nj)
        bs[nj] = *reinterpret_cast<const float2*>(g_Bias + n0 + nj * 8 + 2 * (lane & 3));

#pragma unroll
    for (int mi = 0; mi < 2; ++mi) {
        const int r0 = b0 + m0 + mi * 16 + (lane >> 2);
#pragma unroll
        for (int nj = 0; nj < 4; ++nj) {
            const int col = n0 + nj * 8 + 2 * (lane & 3);
            float2 v0 = make_float2(acc[mi][nj][0] + bs[nj].x, acc[mi][nj][1] + bs[nj].y);
            float2 v1 = make_float2(acc[mi][nj][2] + bs[nj].x, acc[mi][nj][3] + bs[nj].y);
            *reinterpret_cast<float2*>(out + (size_t)r0 * DIM + col)       = v0;
            *reinterpret_cast<float2*>(out + (size_t)(r0 + 8) * DIM + col) = v1;
        }
    }
}

// ---------------- launch ----------------
extern "C" void kernel_launch(void* const* d_in, const int* in_sizes, int n_in,
                              void* d_out, int out_size) {
    const float* x     = (const float*)d_in[0];   // [8192, 128] fp32
    const float* coeff = (const float*)d_in[1];   // [16384, 4]  fp32
    float* out = (float*)d_out;                   // [8192, 128] fp32

    cudaFuncSetAttribute(kan_mma, cudaFuncAttributeMaxDynamicSharedMemorySize, SMEM_TOTAL);

    prep_kernel<<<64, 256>>>(coeff);
    kan_mma<<<NCTA, THREADS, SMEM_TOTAL>>>(x, out);
}

// round 5
// speedup vs baseline: 1.0152x; 1.0152x over previous
#include <cuda_runtime.h>
#include <cuda_bf16.h>
#include <cstdint>

// Problem dims
#define BATCH    8192
#define DIM      128          // in_dim == out_dim
#define KTOT     384          // 3 powers * 128 inputs
#define KC       64           // K per chunk
#define NCHUNK   6
#define MTILE    64           // batch rows per CTA
#define THREADS  512          // 16 warps: 4 (m) x 4 (n)
#define NCTA     (BATCH / MTILE)   // 128

// Chunk order: c = half*3 + pw  (half = j>=64, pw = degree-1)
// Pre-split coefficients in PERMUTED K order: g_B*[o*384 + c*64 + (j&63)]
__device__ __nv_bfloat16 g_Bh[DIM * KTOT];
__device__ __nv_bfloat16 g_Bl[DIM * KTOT];
__device__ float g_Bias[DIM];

// smem buffer layout (per buffer):
//   Ah [64][64]bf16 @ 0      (8 KB)
//   Al [64][64]bf16 @ 8192   (8 KB)
//   Bh [128][64]bf16 @ 16384 (16 KB)
//   Bl [128][64]bf16 @ 32768 (16 KB)
#define REG_AL 8192u
#define REG_BH 16384u
#define REG_BL 32768u
#define BUF_STRIDE 49152u
#define SMEM_TOTAL (2 * BUF_STRIDE)

// ---------------- helpers ----------------
__device__ __forceinline__ uint32_t smem_u32(const void* p) {
    uint32_t a;
    asm("{ .reg .u64 t; cvta.to.shared.u64 t, %1; cvt.u32.u64 %0, t; }" : "=r"(a) : "l"(p));
    return a;
}
__device__ __forceinline__ uint32_t swz128(uint32_t off) { return off ^ ((off >> 3) & 0x70); }

#define CP_ASYNC16(dst_u32, src_ptr)                                              \
    asm volatile("{ .reg .u64 g; cvta.to.global.u64 g, %1;\n"                     \
                 "cp.async.cg.shared.global [%0], [g], 16; }"                     \
                 :: "r"(dst_u32), "l"(src_ptr) : "memory")
#define CP_COMMIT() asm volatile("cp.async.commit_group;" ::: "memory")
#define CP_WAIT0()  asm volatile("cp.async.wait_group 0;" ::: "memory")

#define LDSM4(r, addr)                                                            \
    asm volatile("ldmatrix.sync.aligned.m8n8.x4.shared.b16 {%0,%1,%2,%3}, [%4];"  \
                 : "=r"((r)[0]), "=r"((r)[1]), "=r"((r)[2]), "=r"((r)[3])         \
                 : "r"(addr))

#define MMA_BF16(c, A, b0v, b1v)                                                  \
    asm volatile("mma.sync.aligned.m16n8k16.row.col.f32.bf16.bf16.f32 "           \
                 "{%0,%1,%2,%3}, {%4,%5,%6,%7}, {%8,%9}, {%0,%1,%2,%3};"          \
                 : "+f"((c)[0]), "+f"((c)[1]), "+f"((c)[2]), "+f"((c)[3])         \
                 : "r"((A)[0]), "r"((A)[1]), "r"((A)[2]), "r"((A)[3]),            \
                   "r"(b0v), "r"(b1v))

__device__ __forceinline__ uint32_t split_pack2(float a, float b, uint32_t& lo_pack) {
    __nv_bfloat16 ha = __float2bfloat16(a), hb = __float2bfloat16(b);
    __nv_bfloat16 la = __float2bfloat16(a - __bfloat162float(ha));
    __nv_bfloat16 lb = __float2bfloat16(b - __bfloat162float(hb));
    lo_pack = (uint32_t)__bfloat16_as_ushort(la) | ((uint32_t)__bfloat16_as_ushort(lb) << 16);
    return (uint32_t)__bfloat16_as_ushort(ha) | ((uint32_t)__bfloat16_as_ushort(hb) << 16);
}

// ---------------- prologue: split coeff (permuted K) + fused bias ----------------
__global__ void prep_kernel(const float* __restrict__ coeff) {
    const int tid = threadIdx.x;
    const int idx = blockIdx.x * 256 + tid;       // edge index [0, 16384)
    const int o = idx >> 7, j = idx & 127;
    float4 cf = reinterpret_cast<const float4*>(coeff)[idx];
    float v[3] = {cf.y, cf.z, cf.w};              // degrees 1..3
    const int cbase = (j >= 64) ? 3 : 0;
#pragma unroll
    for (int pw = 0; pw < 3; ++pw) {
        float w = v[pw];
        __nv_bfloat16 h = __float2bfloat16(w);
        __nv_bfloat16 l = __float2bfloat16(w - __bfloat162float(h));
        int off = o * KTOT + (cbase + pw) * 64 + (j & 63);
        g_Bh[off] = h;
        g_Bl[off] = l;
    }
    // bias = sum over j of degree-0 coeff, 128 threads per o
    float s = cf.x;
#pragma unroll
    for (int off = 16; off; off >>= 1)
        s += __shfl_xor_sync(0xffffffffu, s, off);
    __shared__ float ps[8];
    if ((tid & 31) == 0) ps[tid >> 5] = s;
    __syncthreads();
    if (tid == 0)   g_Bias[o] = ps[0] + ps[1] + ps[2] + ps[3];
    if (tid == 128) g_Bias[o] = ps[4] + ps[5] + ps[6] + ps[7];
}

// ---------------- main kernel ----------------
__global__ void __launch_bounds__(THREADS, 1)
kan_mma(const float* __restrict__ x, float* __restrict__ out) {
    extern __shared__ char smem[];
    const uint32_t sb = smem_u32(smem);
    const int tid  = threadIdx.x;
    const int lane = tid & 31;
    const int wid  = tid >> 5;
    const int b0   = blockIdx.x * MTILE;

    // staging thread map: row sr (0..63), eighth sq (0..7) -> 8 consecutive j
    const int sr = tid >> 3;
    const int sq = tid & 7;

    // warp tile coords (16 x 32): 4 m-warps x 4 n-warps
    const int m0 = (wid & 3) * 16;
    const int n0 = (wid >> 2) * 32;

    float acc[4][4];
#pragma unroll
    for (int nj = 0; nj < 4; ++nj)
#pragma unroll
        for (int i = 0; i < 4; ++i) acc[nj][i] = 0.f;

    float4 xv[2];     // current j-half of x (8 floats), persists across 3 chunks
    float  w[8];      // running power x^(pw+1)

    // ---- staging helpers ----
    auto issue_B = [&](int cn, uint32_t tb) {
#pragma unroll
        for (int i = 0; i < 2; ++i) {
            int idx = tid + i * THREADS;          // 0..1023
            int n = idx >> 3, k8 = idx & 7;
            const __nv_bfloat16* srcH = g_Bh + n * KTOT + cn * KC + k8 * 8;
            const __nv_bfloat16* srcL = g_Bl + n * KTOT + cn * KC + k8 * 8;
            uint32_t sw = swz128((uint32_t)(n * 128 + k8 * 16));
            CP_ASYNC16(sb + tb + REG_BH + sw, srcH);
            CP_ASYNC16(sb + tb + REG_BL + sw, srcL);
        }
    };
    auto issue_X = [&](int cn) {                  // only for cn % 3 == 0
        const int jhalf = (cn / 3) * 64;
        const float4* xs = reinterpret_cast<const float4*>(
            x + (size_t)(b0 + sr) * DIM + jhalf + sq * 8);
        xv[0] = xs[0];
        xv[1] = xs[1];
    };
    auto store_A = [&](int cn, uint32_t tb) {
        if (cn % 3 == 0) {
            w[0] = xv[0].x; w[1] = xv[0].y; w[2] = xv[0].z; w[3] = xv[0].w;
            w[4] = xv[1].x; w[5] = xv[1].y; w[6] = xv[1].z; w[7] = xv[1].w;
        } else {
            w[0] *= xv[0].x; w[1] *= xv[0].y; w[2] *= xv[0].z; w[3] *= xv[0].w;
            w[4] *= xv[1].x; w[5] *= xv[1].y; w[6] *= xv[1].z; w[7] *= xv[1].w;
        }
        uint32_t hp[4], lp[4];
#pragma unroll
        for (int i = 0; i < 4; ++i) hp[i] = split_pack2(w[2 * i], w[2 * i + 1], lp[i]);
        uint32_t base = swz128((uint32_t)(sr * 128 + sq * 16));
        *reinterpret_cast<uint4*>(smem + tb + base) =
            make_uint4(hp[0], hp[1], hp[2], hp[3]);
        *reinterpret_cast<uint4*>(smem + tb + REG_AL + base) =
            make_uint4(lp[0], lp[1], lp[2], lp[3]);
    };

    // ---- prologue: stage chunk 0 ----
    issue_B(0, 0);
    CP_COMMIT();
    issue_X(0);
    store_A(0, 0);
    CP_WAIT0();
    __syncthreads();

    // per-lane ldmatrix base coords
    const uint32_t a_row = (uint32_t)(m0 + (lane & 15));
    const uint32_t a_kb  = (uint32_t)((lane >> 4) * 16);
    const uint32_t b_row = (uint32_t)(n0 + (lane & 7) + ((lane >> 4) << 3));
    const uint32_t b_kb  = (uint32_t)(((lane >> 3) & 1) * 16);

    auto load_frags = [&](uint32_t tb, int ks, uint32_t ah[4], uint32_t al[4],
                          uint32_t bh[2][4], uint32_t bl[2][4]) {
        {
            uint32_t off = a_row * 128 + ks * 32 + a_kb;
            LDSM4(ah, sb + tb + swz128(off));
            LDSM4(al, sb + tb + REG_AL + swz128(off));
        }
#pragma unroll
        for (int ni = 0; ni < 2; ++ni) {
            uint32_t off = (b_row + ni * 16) * 128 + ks * 32 + b_kb;
            LDSM4(bh[ni], sb + tb + REG_BH + swz128(off));
            LDSM4(bl[ni], sb + tb + REG_BL + swz128(off));
        }
    };
    // term-major: 4 independent accs between touches of the same acc
    auto mma_all = [&](uint32_t ah[4], uint32_t al[4],
                       uint32_t bh[2][4], uint32_t bl[2][4]) {
#pragma unroll
        for (int nj = 0; nj < 4; ++nj) {
            const int ni = nj >> 1, br = (nj & 1) * 2;
            MMA_BF16(acc[nj], ah, bh[ni][br], bh[ni][br + 1]);
        }
#pragma unroll
        for (int nj = 0; nj < 4; ++nj) {
            const int ni = nj >> 1, br = (nj & 1) * 2;
            MMA_BF16(acc[nj], al, bh[ni][br], bh[ni][br + 1]);
        }
#pragma unroll
        for (int nj = 0; nj < 4; ++nj) {
            const int ni = nj >> 1, br = (nj & 1) * 2;
            MMA_BF16(acc[nj], ah, bl[ni][br], bl[ni][br + 1]);
        }
    };

    for (int c = 0; c < NCHUNK; ++c) {
        const uint32_t tb  = (uint32_t)(c & 1) * BUF_STRIDE;
        const uint32_t tbn = (uint32_t)((c + 1) & 1) * BUF_STRIDE;

        if (c + 1 < NCHUNK) {
            issue_B(c + 1, tbn);
            CP_COMMIT();
            if ((c + 1) % 3 == 0) issue_X(c + 1);
        }

        // ---- fragment-pipelined MMA over 4 k16-steps ----
        {
            uint32_t ah0[4], al0[4], bh0[2][4], bl0[2][4];
            uint32_t ah1[4], al1[4], bh1[2][4], bl1[2][4];
            load_frags(tb, 0, ah0, al0, bh0, bl0);
            load_frags(tb, 1, ah1, al1, bh1, bl1);
            mma_all(ah0, al0, bh0, bl0);
            load_frags(tb, 2, ah0, al0, bh0, bl0);
            mma_all(ah1, al1, bh1, bl1);
            load_frags(tb, 3, ah1, al1, bh1, bl1);
            mma_all(ah0, al0, bh0, bl0);
            mma_all(ah1, al1, bh1, bl1);
        }

        if (c + 1 < NCHUNK) {
            store_A(c + 1, tbn);
            CP_WAIT0();
        }
        __syncthreads();
    }

    // ---- epilogue: bias + store ----
    float2 bs[4];
#pragma unroll
    for (int nj = 0; nj < 4; ++nj)
        bs[nj] = *reinterpret_cast<const float2*>(g_Bias + n0 + nj * 8 + 2 * (lane & 3));

    const int r0 = b0 + m0 + (lane >> 2);
#pragma unroll
    for (int nj = 0; nj < 4; ++nj) {
        const int col = n0 + nj * 8 + 2 * (lane & 3);
        float2 v0 = make_float2(acc[nj][0] + bs[nj].x, acc[nj][1] + bs[nj].y);
        float2 v1 = make_float2(acc[nj][2] + bs[nj].x, acc[nj][3] + bs[nj].y);
        *reinterpret_cast<float2*>(out + (size_t)r0 * DIM + col)       = v0;
        *reinterpret_cast<float2*>(out + (size_t)(r0 + 8) * DIM + col) = v1;
    }
}

// ---------------- launch ----------------
extern "C" void kernel_launch(void* const* d_in, const int* in_sizes, int n_in,
                              void* d_out, int out_size) {
    const float* x     = (const float*)d_in[0];   // [8192, 128] fp32
    const float* coeff = (const float*)d_in[1];   // [16384, 4]  fp32
    float* out = (float*)d_out;                   // [8192, 128] fp32

    cudaFuncSetAttribute(kan_mma, cudaFuncAttributeMaxDynamicSharedMemorySize, SMEM_TOTAL);

    prep_kernel<<<64, 256>>>(coeff);
    kan_mma<<<NCTA, THREADS, SMEM_TOTAL>>>(x, out);
}

// round 6
// speedup vs baseline: 1.0171x; 1.0019x over previous
#include <cuda_runtime.h>
#include <cuda_bf16.h>
#include <cstdint>

// Problem dims
#define BATCH    8192
#define DIM      128          // in_dim == out_dim
#define KTOT     384          // 3 powers * 128 inputs, permuted: k = (half*3+pw)*64 + (j&63)
#define KC       64           // K per chunk
#define NCHUNK   6
#define MTILE    64           // batch rows per CTA
#define THREADS  512          // 16 warps: 4 (m) x 4 (n)
#define NCTA     (BATCH / MTILE)   // 128
#define NSTAGE   3

// Pre-split operands (permuted K order)
__device__ __nv_bfloat16 g_Ah[BATCH * KTOT];   // 6 MB
__device__ __nv_bfloat16 g_Al[BATCH * KTOT];   // 6 MB
__device__ __nv_bfloat16 g_Bh[DIM * KTOT];
__device__ __nv_bfloat16 g_Bl[DIM * KTOT];
__device__ float g_Bias[DIM];

// smem stage layout: Ah[64][64] @0 (8K), Al @8192, Bh[128][64] @16384 (16K), Bl @32768
#define REG_AL 8192u
#define REG_BH 16384u
#define REG_BL 32768u
#define BUF_STRIDE 49152u
#define SMEM_TOTAL (NSTAGE * BUF_STRIDE)   // 144 KB

// ---------------- helpers ----------------
__device__ __forceinline__ uint32_t smem_u32(const void* p) {
    uint32_t a;
    asm("{ .reg .u64 t; cvta.to.shared.u64 t, %1; cvt.u32.u64 %0, t; }" : "=r"(a) : "l"(p));
    return a;
}
__device__ __forceinline__ uint32_t swz128(uint32_t off) { return off ^ ((off >> 3) & 0x70); }

#define CP_ASYNC16(dst_u32, src_ptr)                                              \
    asm volatile("{ .reg .u64 g; cvta.to.global.u64 g, %1;\n"                     \
                 "cp.async.cg.shared.global [%0], [g], 16; }"                     \
                 :: "r"(dst_u32), "l"(src_ptr) : "memory")
#define CP_COMMIT()  asm volatile("cp.async.commit_group;" ::: "memory")
#define CP_WAITG(n)  asm volatile("cp.async.wait_group %0;" :: "n"(n) : "memory")

#define LDSM4(r, addr)                                                            \
    asm volatile("ldmatrix.sync.aligned.m8n8.x4.shared.b16 {%0,%1,%2,%3}, [%4];"  \
                 : "=r"((r)[0]), "=r"((r)[1]), "=r"((r)[2]), "=r"((r)[3])         \
                 : "r"(addr))

#define MMA_BF16(c, A, b0v, b1v)                                                  \
    asm volatile("mma.sync.aligned.m16n8k16.row.col.f32.bf16.bf16.f32 "           \
                 "{%0,%1,%2,%3}, {%4,%5,%6,%7}, {%8,%9}, {%0,%1,%2,%3};"          \
                 : "+f"((c)[0]), "+f"((c)[1]), "+f"((c)[2]), "+f"((c)[3])         \
                 : "r"((A)[0]), "r"((A)[1]), "r"((A)[2]), "r"((A)[3]),            \
                   "r"(b0v), "r"(b1v))

__device__ __forceinline__ uint32_t split_pack2(float a, float b, uint32_t& lo_pack) {
    __nv_bfloat16 ha = __float2bfloat16(a), hb = __float2bfloat16(b);
    __nv_bfloat16 la = __float2bfloat16(a - __bfloat162float(ha));
    __nv_bfloat16 lb = __float2bfloat16(b - __bfloat162float(hb));
    lo_pack = (uint32_t)__bfloat16_as_ushort(la) | ((uint32_t)__bfloat16_as_ushort(lb) << 16);
    return (uint32_t)__bfloat16_as_ushort(ha) | ((uint32_t)__bfloat16_as_ushort(hb) << 16);
}

// ---------------- prologue: split coeff + bias + precompute split A ----------------
__global__ void prep_kernel(const float* __restrict__ x, const float* __restrict__ coeff) {
    const int bid = blockIdx.x;
    const int tid = threadIdx.x;
    if (bid < 64) {
        // --- coeff split (permuted K) + bias ---
        const int idx = bid * 256 + tid;          // edge index [0, 16384)
        const int o = idx >> 7, j = idx & 127;
        float4 cf = reinterpret_cast<const float4*>(coeff)[idx];
        float v[3] = {cf.y, cf.z, cf.w};          // degrees 1..3
        const int cbase = (j >= 64) ? 3 : 0;
#pragma unroll
        for (int pw = 0; pw < 3; ++pw) {
            float w = v[pw];
            __nv_bfloat16 h = __float2bfloat16(w);
            __nv_bfloat16 l = __float2bfloat16(w - __bfloat162float(h));
            int off = o * KTOT + (cbase + pw) * 64 + (j & 63);
            g_Bh[off] = h;
            g_Bl[off] = l;
        }
        float s = cf.x;
#pragma unroll
        for (int off = 16; off; off >>= 1)
            s += __shfl_xor_sync(0xffffffffu, s, off);
        __shared__ float ps[8];
        if ((tid & 31) == 0) ps[tid >> 5] = s;
        __syncthreads();
        if (tid == 0)   g_Bias[o] = ps[0] + ps[1] + ps[2] + ps[3];
        if (tid == 128) g_Bias[o] = ps[4] + ps[5] + ps[6] + ps[7];
    } else {
        // --- A precompute: powers of x, split hi/lo, permuted K layout ---
        const int t = (bid - 64) * 256 + tid;     // [0, 65536)
#pragma unroll
        for (int i = 0; i < 4; ++i) {
            int f4 = t + i * 65536;               // float4 index over x [0, 262144)
            int b = f4 >> 5, j4 = f4 & 31;        // j = j4*4
            float4 v = reinterpret_cast<const float4*>(x)[f4];
            long obase = (long)b * KTOT + ((j4 >= 16) ? 192 : 0) + (j4 & 15) * 4;
            float p0 = v.x, p1 = v.y, p2 = v.z, p3 = v.w;
#pragma unroll
            for (int pw = 0; pw < 3; ++pw) {
                uint32_t h0, h1, l0, l1;
                h0 = split_pack2(p0, p1, l0);
                h1 = split_pack2(p2, p3, l1);
                *reinterpret_cast<uint2*>(g_Ah + obase + pw * 64) = make_uint2(h0, h1);
                *reinterpret_cast<uint2*>(g_Al + obase + pw * 64) = make_uint2(l0, l1);
                p0 *= v.x; p1 *= v.y; p2 *= v.z; p3 *= v.w;
            }
        }
    }
}

// ---------------- main kernel: pure multistage cp.async GEMM ----------------
__global__ void __launch_bounds__(THREADS, 1)
kan_mma(float* __restrict__ out) {
    extern __shared__ char smem[];
    const uint32_t sb = smem_u32(smem);
    const int tid  = threadIdx.x;
    const int lane = tid & 31;
    const int wid  = tid >> 5;
    const int b0   = blockIdx.x * MTILE;

    // warp tile coords (16 x 32): 4 m-warps x 4 n-warps
    const int m0 = (wid & 3) * 16;
    const int n0 = (wid >> 2) * 32;

    float acc[4][4];
#pragma unroll
    for (int nj = 0; nj < 4; ++nj)
#pragma unroll
        for (int i = 0; i < 4; ++i) acc[nj][i] = 0.f;

    // ---- per-thread cp.async source/dst precompute ----
    // A: 1024 16B loads (Ah 512 + Al 512): idx = tid + s*512, s=0..1
    //    r = (idx&511)>>3, k8 = idx&7
    // B: 2048 16B loads (Bh 1024 + Bl 1024): idx = tid + s*512, s=0..3
    //    n = (idx&1023)>>3, k8 = idx&7
    auto issue_stage = [&](int cn, uint32_t tb) {
#pragma unroll
        for (int s = 0; s < 2; ++s) {
            int idx = tid + s * THREADS;
            int r = (idx & 511) >> 3, k8 = idx & 7;
            const __nv_bfloat16* src =
                (idx < 512 ? g_Ah : g_Al) + (size_t)(b0 + r) * KTOT + cn * KC + k8 * 8;
            uint32_t dst = tb + (idx < 512 ? 0u : REG_AL)
                         + swz128((uint32_t)(r * 128 + k8 * 16));
            CP_ASYNC16(sb + dst, src);
        }
#pragma unroll
        for (int s = 0; s < 4; ++s) {
            int idx = tid + s * THREADS;
            int n = (idx & 1023) >> 3, k8 = idx & 7;
            const __nv_bfloat16* src =
                (idx < 1024 ? g_Bh : g_Bl) + (size_t)n * KTOT + cn * KC + k8 * 8;
            uint32_t dst = tb + (idx < 1024 ? REG_BH : REG_BL)
                         + swz128((uint32_t)(n * 128 + k8 * 16));
            CP_ASYNC16(sb + dst, src);
        }
    };

    // per-lane ldmatrix base coords
    const uint32_t a_row = (uint32_t)(m0 + (lane & 15));
    const uint32_t a_kb  = (uint32_t)((lane >> 4) * 16);
    const uint32_t b_row = (uint32_t)(n0 + (lane & 7) + ((lane >> 4) << 3));
    const uint32_t b_kb  = (uint32_t)(((lane >> 3) & 1) * 16);

    auto load_frags = [&](uint32_t tb, int ks, uint32_t ah[4], uint32_t al[4],
                          uint32_t bh[2][4], uint32_t bl[2][4]) {
        {
            uint32_t off = a_row * 128 + ks * 32 + a_kb;
            LDSM4(ah, sb + tb + swz128(off));
            LDSM4(al, sb + tb + REG_AL + swz128(off));
        }
#pragma unroll
        for (int ni = 0; ni < 2; ++ni) {
            uint32_t off = (b_row + ni * 16) * 128 + ks * 32 + b_kb;
            LDSM4(bh[ni], sb + tb + REG_BH + swz128(off));
            LDSM4(bl[ni], sb + tb + REG_BL + swz128(off));
        }
    };
    auto mma_all = [&](uint32_t ah[4], uint32_t al[4],
                       uint32_t bh[2][4], uint32_t bl[2][4]) {
#pragma unroll
        for (int nj = 0; nj < 4; ++nj) {
            const int ni = nj >> 1, br = (nj & 1) * 2;
            MMA_BF16(acc[nj], ah, bh[ni][br], bh[ni][br + 1]);
        }
#pragma unroll
        for (int nj = 0; nj < 4; ++nj) {
            const int ni = nj >> 1, br = (nj & 1) * 2;
            MMA_BF16(acc[nj], al, bh[ni][br], bh[ni][br + 1]);
        }
#pragma unroll
        for (int nj = 0; nj < 4; ++nj) {
            const int ni = nj >> 1, br = (nj & 1) * 2;
            MMA_BF16(acc[nj], ah, bl[ni][br], bl[ni][br + 1]);
        }
    };

    // ---- prologue: 2 stages in flight ----
    issue_stage(0, 0);
    CP_COMMIT();
    issue_stage(1, BUF_STRIDE);
    CP_COMMIT();

#pragma unroll
    for (int c = 0; c < NCHUNK; ++c) {
        // wait for stage c, then one barrier (also protects buffer (c-1)%3 reuse)
        if (c < NCHUNK - 1) CP_WAITG(1); else CP_WAITG(0);
        __syncthreads();

        if (c + 2 < NCHUNK) {
            issue_stage(c + 2, (uint32_t)((c + 2) % NSTAGE) * BUF_STRIDE);
            CP_COMMIT();
        }

        const uint32_t tb = (uint32_t)(c % NSTAGE) * BUF_STRIDE;
        uint32_t ah0[4], al0[4], bh0[2][4], bl0[2][4];
        uint32_t ah1[4], al1[4], bh1[2][4], bl1[2][4];
        load_frags(tb, 0, ah0, al0, bh0, bl0);
        load_frags(tb, 1, ah1, al1, bh1, bl1);
        mma_all(ah0, al0, bh0, bl0);
        load_frags(tb, 2, ah0, al0, bh0, bl0);
        mma_all(ah1, al1, bh1, bl1);
        load_frags(tb, 3, ah1, al1, bh1, bl1);
        mma_all(ah0, al0, bh0, bl0);
        mma_all(ah1, al1, bh1, bl1);
    }

    // ---- epilogue: bias + store ----
    float2 bs[4];
#pragma unroll
    for (int nj = 0; nj < 4; ++nj)
        bs[nj] = *reinterpret_cast<const float2*>(g_Bias + n0 + nj * 8 + 2 * (lane & 3));

    const int r0 = b0 + m0 + (lane >> 2);
#pragma unroll
    for (int nj = 0; nj < 4; ++nj) {
        const int col = n0 + nj * 8 + 2 * (lane & 3);
        float2 v0 = make_float2(acc[nj][0] + bs[nj].x, acc[nj][1] + bs[nj].y);
        float2 v1 = make_float2(acc[nj][2] + bs[nj].x, acc[nj][3] + bs[nj].y);
        *reinterpret_cast<float2*>(out + (size_t)r0 * DIM + col)       = v0;
        *reinterpret_cast<float2*>(out + (size_t)(r0 + 8) * DIM + col) = v1;
    }
}

// ---------------- launch ----------------
extern "C" void kernel_launch(void* const* d_in, const int* in_sizes, int n_in,
                              void* d_out, int out_size) {
    const float* x     = (const float*)d_in[0];   // [8192, 128] fp32
    const float* coeff = (const float*)d_in[1];   // [16384, 4]  fp32
    float* out = (float*)d_out;                   // [8192, 128] fp32

    cudaFuncSetAttribute(kan_mma, cudaFuncAttributeMaxDynamicSharedMemorySize, SMEM_TOTAL);

    prep_kernel<<<320, 256>>>(x, coeff);
    kan_mma<<<NCTA, THREADS, SMEM_TOTAL>>>(out);
}

// round 7
// speedup vs baseline: 1.1577x; 1.1382x over previous
#include <cuda_runtime.h>
#include <cuda_bf16.h>
#include <cstdint>

// Problem dims
#define BATCH    8192
#define DIM      128          // in_dim == out_dim
#define KTOT     384          // permuted K: k = (half*3+pw)*64 + (j&63)
#define KC       64           // K per chunk
#define NCHUNK   6
#define MTILE    64           // batch rows per CTA
#define THREADS  512          // 16 warps: 4 (m) x 4 (n)
#define NCTA     (BATCH / MTILE)   // 128
#define NSTAGE   3

// Pre-split coefficients (permuted K order): g_B*[o*384 + c*64 + (j&63)]
__device__ __nv_bfloat16 g_Bh[DIM * KTOT];
__device__ __nv_bfloat16 g_Bl[DIM * KTOT];
__device__ float g_Bias[DIM];

// smem layout:
//   A chunks: 6 x { Ah[64][64]bf16 (8K) @ c*16384, Al (8K) @ c*16384+8192 }  = 96 KB
//   B stages: 3 x { Bh[128][64]bf16 (16K), Bl (16K) } @ 98304 + s*32768     = 96 KB
#define A_CHUNK_STRIDE 16384u
#define A_LO_OFF       8192u
#define B_BASE         98304u
#define B_LO_OFF       16384u
#define B_STAGE_STRIDE 32768u
#define SMEM_TOTAL     196608   // 192 KB

// ---------------- helpers ----------------
__device__ __forceinline__ uint32_t smem_u32(const void* p) {
    uint32_t a;
    asm("{ .reg .u64 t; cvta.to.shared.u64 t, %1; cvt.u32.u64 %0, t; }" : "=r"(a) : "l"(p));
    return a;
}
__device__ __forceinline__ uint32_t swz128(uint32_t off) { return off ^ ((off >> 3) & 0x70); }

#define CP_ASYNC16(dst_u32, src_ptr)                                              \
    asm volatile("{ .reg .u64 g; cvta.to.global.u64 g, %1;\n"                     \
                 "cp.async.cg.shared.global [%0], [g], 16; }"                     \
                 :: "r"(dst_u32), "l"(src_ptr) : "memory")
#define CP_COMMIT()  asm volatile("cp.async.commit_group;" ::: "memory")
#define CP_WAITG(n)  asm volatile("cp.async.wait_group %0;" :: "n"(n) : "memory")

#define LDSM4(r, addr)                                                            \
    asm volatile("ldmatrix.sync.aligned.m8n8.x4.shared.b16 {%0,%1,%2,%3}, [%4];"  \
                 : "=r"((r)[0]), "=r"((r)[1]), "=r"((r)[2]), "=r"((r)[3])         \
                 : "r"(addr))

#define MMA_BF16(c, A, b0v, b1v)                                                  \
    asm volatile("mma.sync.aligned.m16n8k16.row.col.f32.bf16.bf16.f32 "           \
                 "{%0,%1,%2,%3}, {%4,%5,%6,%7}, {%8,%9}, {%0,%1,%2,%3};"          \
                 : "+f"((c)[0]), "+f"((c)[1]), "+f"((c)[2]), "+f"((c)[3])         \
                 : "r"((A)[0]), "r"((A)[1]), "r"((A)[2]), "r"((A)[3]),            \
                   "r"(b0v), "r"(b1v))

__device__ __forceinline__ uint32_t split_pack2(float a, float b, uint32_t& lo_pack) {
    __nv_bfloat16 ha = __float2bfloat16(a), hb = __float2bfloat16(b);
    __nv_bfloat16 la = __float2bfloat16(a - __bfloat162float(ha));
    __nv_bfloat16 lb = __float2bfloat16(b - __bfloat162float(hb));
    lo_pack = (uint32_t)__bfloat16_as_ushort(la) | ((uint32_t)__bfloat16_as_ushort(lb) << 16);
    return (uint32_t)__bfloat16_as_ushort(ha) | ((uint32_t)__bfloat16_as_ushort(hb) << 16);
}

// ---------------- prologue: split coeff (permuted K) + fused bias ----------------
__global__ void prep_kernel(const float* __restrict__ coeff) {
    const int tid = threadIdx.x;
    const int idx = blockIdx.x * 256 + tid;       // edge index [0, 16384)
    const int o = idx >> 7, j = idx & 127;
    float4 cf = reinterpret_cast<const float4*>(coeff)[idx];
    float v[3] = {cf.y, cf.z, cf.w};              // degrees 1..3
    const int cbase = (j >= 64) ? 3 : 0;
#pragma unroll
    for (int pw = 0; pw < 3; ++pw) {
        float w = v[pw];
        __nv_bfloat16 h = __float2bfloat16(w);
        __nv_bfloat16 l = __float2bfloat16(w - __bfloat162float(h));
        int off = o * KTOT + (cbase + pw) * 64 + (j & 63);
        g_Bh[off] = h;
        g_Bl[off] = l;
    }
    float s = cf.x;
#pragma unroll
    for (int off = 16; off; off >>= 1)
        s += __shfl_xor_sync(0xffffffffu, s, off);
    __shared__ float ps[8];
    if ((tid & 31) == 0) ps[tid >> 5] = s;
    __syncthreads();
    if (tid == 0)   g_Bias[o] = ps[0] + ps[1] + ps[2] + ps[3];
    if (tid == 128) g_Bias[o] = ps[4] + ps[5] + ps[6] + ps[7];
}

// ---------------- main kernel ----------------
__global__ void __launch_bounds__(THREADS, 1)
kan_mma(const float* __restrict__ x, float* __restrict__ out) {
    extern __shared__ char smem[];
    const uint32_t sb = smem_u32(smem);
    const int tid  = threadIdx.x;
    const int lane = tid & 31;
    const int wid  = tid >> 5;
    const int b0   = blockIdx.x * MTILE;

    // warp tile coords (16 x 32): 4 m-warps x 4 n-warps
    const int m0 = (wid & 3) * 16;
    const int n0 = (wid >> 2) * 32;

    float acc[4][4];
#pragma unroll
    for (int nj = 0; nj < 4; ++nj)
#pragma unroll
        for (int i = 0; i < 4; ++i) acc[nj][i] = 0.f;

    // ---- B stage loader: 2048 16B loads / 512 threads = 4 each ----
    auto issue_B = [&](int cn, uint32_t tb) {
#pragma unroll
        for (int s = 0; s < 4; ++s) {
            int idx = tid + s * THREADS;          // 0..2047
            int n = (idx & 1023) >> 3, k8 = idx & 7;
            const __nv_bfloat16* src =
                (idx < 1024 ? g_Bh : g_Bl) + (size_t)n * KTOT + cn * KC + k8 * 8;
            uint32_t dst = tb + (idx < 1024 ? 0u : B_LO_OFF)
                         + swz128((uint32_t)(n * 128 + k8 * 16));
            CP_ASYNC16(sb + dst, src);
        }
    };

    // ---- issue first two B stages, then build the full A tile ----
    issue_B(0, B_BASE);
    CP_COMMIT();
    issue_B(1, B_BASE + B_STAGE_STRIDE);
    CP_COMMIT();

    // Build A: thread handles row sr (0..63), j-octet sq (0..7) of BOTH halves.
    // For each half h and power pw: chunk = h*3+pw, value x^(pw+1) split hi/lo.
    {
        const int sr = tid >> 3;
        const int sq = tid & 7;
        const float4* xr = reinterpret_cast<const float4*>(
            x + (size_t)(b0 + sr) * DIM);
        const uint32_t abase = swz128((uint32_t)(sr * 128 + sq * 16));
#pragma unroll
        for (int h = 0; h < 2; ++h) {
            float4 v0 = xr[h * 16 + sq * 2];
            float4 v1 = xr[h * 16 + sq * 2 + 1];
            float w[8] = {v0.x, v0.y, v0.z, v0.w, v1.x, v1.y, v1.z, v1.w};
#pragma unroll
            for (int pw = 0; pw < 3; ++pw) {
                uint32_t hp[4], lp[4];
#pragma unroll
                for (int i = 0; i < 4; ++i)
                    hp[i] = split_pack2(w[2 * i], w[2 * i + 1], lp[i]);
                const uint32_t cb = (uint32_t)(h * 3 + pw) * A_CHUNK_STRIDE;
                *reinterpret_cast<uint4*>(smem + cb + abase) =
                    make_uint4(hp[0], hp[1], hp[2], hp[3]);
                *reinterpret_cast<uint4*>(smem + cb + A_LO_OFF + abase) =
                    make_uint4(lp[0], lp[1], lp[2], lp[3]);
                if (pw < 2) {
                    w[0] *= v0.x; w[1] *= v0.y; w[2] *= v0.z; w[3] *= v0.w;
                    w[4] *= v1.x; w[5] *= v1.y; w[6] *= v1.z; w[7] *= v1.w;
                }
            }
        }
    }
    __syncthreads();   // A visible to all warps

    // per-lane ldmatrix base coords
    const uint32_t a_row = (uint32_t)(m0 + (lane & 15));
    const uint32_t a_kb  = (uint32_t)((lane >> 4) * 16);
    const uint32_t b_row = (uint32_t)(n0 + (lane & 7) + ((lane >> 4) << 3));
    const uint32_t b_kb  = (uint32_t)(((lane >> 3) & 1) * 16);

    auto load_frags = [&](uint32_t ab, uint32_t bb, int ks,
                          uint32_t ah[4], uint32_t al[4],
                          uint32_t bh[2][4], uint32_t bl[2][4]) {
        {
            uint32_t off = swz128(a_row * 128 + ks * 32 + a_kb);
            LDSM4(ah, sb + ab + off);
            LDSM4(al, sb + ab + A_LO_OFF + off);
        }
#pragma unroll
        for (int ni = 0; ni < 2; ++ni) {
            uint32_t off = swz128((b_row + ni * 16) * 128 + ks * 32 + b_kb);
            LDSM4(bh[ni], sb + bb + off);
            LDSM4(bl[ni], sb + bb + B_LO_OFF + off);
        }
    };
    auto mma_all = [&](uint32_t ah[4], uint32_t al[4],
                       uint32_t bh[2][4], uint32_t bl[2][4]) {
#pragma unroll
        for (int nj = 0; nj < 4; ++nj) {
            const int ni = nj >> 1, br = (nj & 1) * 2;
            MMA_BF16(acc[nj], ah, bh[ni][br], bh[ni][br + 1]);
        }
#pragma unroll
        for (int nj = 0; nj < 4; ++nj) {
            const int ni = nj >> 1, br = (nj & 1) * 2;
            MMA_BF16(acc[nj], al, bh[ni][br], bh[ni][br + 1]);
        }
#pragma unroll
        for (int nj = 0; nj < 4; ++nj) {
            const int ni = nj >> 1, br = (nj & 1) * 2;
            MMA_BF16(acc[nj], ah, bl[ni][br], bl[ni][br + 1]);
        }
    };

#pragma unroll
    for (int c = 0; c < NCHUNK; ++c) {
        if (c < NCHUNK - 1) CP_WAITG(1); else CP_WAITG(0);
        __syncthreads();   // stage c visible; buffer (c+2)%3 free for overwrite

        if (c + 2 < NCHUNK) {
            issue_B(c + 2, B_BASE + (uint32_t)((c + 2) % NSTAGE) * B_STAGE_STRIDE);
            CP_COMMIT();
        }

        const uint32_t ab = (uint32_t)c * A_CHUNK_STRIDE;
        const uint32_t bb = B_BASE + (uint32_t)(c % NSTAGE) * B_STAGE_STRIDE;
        uint32_t ah0[4], al0[4], bh0[2][4], bl0[2][4];
        uint32_t ah1[4], al1[4], bh1[2][4], bl1[2][4];
        load_frags(ab, bb, 0, ah0, al0, bh0, bl0);
        load_frags(ab, bb, 1, ah1, al1, bh1, bl1);
        mma_all(ah0, al0, bh0, bl0);
        load_frags(ab, bb, 2, ah0, al0, bh0, bl0);
        mma_all(ah1, al1, bh1, bl1);
        load_frags(ab, bb, 3, ah1, al1, bh1, bl1);
        mma_all(ah0, al0, bh0, bl0);
        mma_all(ah1, al1, bh1, bl1);
    }

    // ---- epilogue: bias + store ----
    float2 bs[4];
#pragma unroll
    for (int nj = 0; nj < 4; ++nj)
        bs[nj] = *reinterpret_cast<const float2*>(g_Bias + n0 + nj * 8 + 2 * (lane & 3));

    const int r0 = b0 + m0 + (lane >> 2);
#pragma unroll
    for (int nj = 0; nj < 4; ++nj) {
        const int col = n0 + nj * 8 + 2 * (lane & 3);
        float2 v0 = make_float2(acc[nj][0] + bs[nj].x, acc[nj][1] + bs[nj].y);
        float2 v1 = make_float2(acc[nj][2] + bs[nj].x, acc[nj][3] + bs[nj].y);
        *reinterpret_cast<float2*>(out + (size_t)r0 * DIM + col)       = v0;
        *reinterpret_cast<float2*>(out + (size_t)(r0 + 8) * DIM + col) = v1;
    }
}

// ---------------- launch ----------------
extern "C" void kernel_launch(void* const* d_in, const int* in_sizes, int n_in,
                              void* d_out, int out_size) {
    const float* x     = (const float*)d_in[0];   // [8192, 128] fp32
    const float* coeff = (const float*)d_in[1];   // [16384, 4]  fp32
    float* out = (float*)d_out;                   // [8192, 128] fp32

    cudaFuncSetAttribute(kan_mma, cudaFuncAttributeMaxDynamicSharedMemorySize, SMEM_TOTAL);

    prep_kernel<<<64, 256>>>(coeff);
    kan_mma<<<NCTA, THREADS, SMEM_TOTAL>>>(x, out);
}

// round 8
// speedup vs baseline: 1.3170x; 1.1376x over previous
#include <cuda_runtime.h>
#include <cuda_fp16.h>
#include <cstdint>

// Problem dims
#define BATCH    8192
#define DIM      128          // in_dim == out_dim
#define KTOT     384          // permuted K: k = (half*3+pw)*64 + (j&63)
#define KC       64           // K per chunk
#define NCHUNK   6
#define MTILE    32           // batch rows per CTA
#define THREADS  256          // 8 warps: 2 (m) x 4 (n)
#define NCTA     (BATCH / MTILE)   // 256
#define NSTAGE   3

// fp16 coefficients (permuted K order): g_Bf[o*384 + c*64 + (j&63)]
__device__ __half g_Bf[DIM * KTOT];
__device__ float g_Bias[DIM];

// smem layout (96 KB total):
//   A chunks: 6 x { Ah[32][64]f16 (4K) @ c*8192, Al (4K) @ c*8192+4096 } = 48 KB
//   B stages: 3 x Bf[128][64]f16 (16K) @ 49152 + s*16384                = 48 KB
#define A_CHUNK_STRIDE 8192u
#define A_LO_OFF       4096u
#define B_BASE         49152u
#define B_STAGE_STRIDE 16384u
#define SMEM_TOTAL     98304   // 96 KB -> 2 CTAs/SM

// ---------------- helpers ----------------
__device__ __forceinline__ uint32_t smem_u32(const void* p) {
    uint32_t a;
    asm("{ .reg .u64 t; cvta.to.shared.u64 t, %1; cvt.u32.u64 %0, t; }" : "=r"(a) : "l"(p));
    return a;
}
__device__ __forceinline__ uint32_t swz128(uint32_t off) { return off ^ ((off >> 3) & 0x70); }

#define CP_ASYNC16(dst_u32, src_ptr)                                              \
    asm volatile("{ .reg .u64 g; cvta.to.global.u64 g, %1;\n"                     \
                 "cp.async.cg.shared.global [%0], [g], 16; }"                     \
                 :: "r"(dst_u32), "l"(src_ptr) : "memory")
#define CP_COMMIT()  asm volatile("cp.async.commit_group;" ::: "memory")
#define CP_WAITG(n)  asm volatile("cp.async.wait_group %0;" :: "n"(n) : "memory")

#define LDSM4(r, addr)                                                            \
    asm volatile("ldmatrix.sync.aligned.m8n8.x4.shared.b16 {%0,%1,%2,%3}, [%4];"  \
                 : "=r"((r)[0]), "=r"((r)[1]), "=r"((r)[2]), "=r"((r)[3])         \
                 : "r"(addr))

#define MMA_F16(c, A, b0v, b1v)                                                   \
    asm volatile("mma.sync.aligned.m16n8k16.row.col.f32.f16.f16.f32 "             \
                 "{%0,%1,%2,%3}, {%4,%5,%6,%7}, {%8,%9}, {%0,%1,%2,%3};"          \
                 : "+f"((c)[0]), "+f"((c)[1]), "+f"((c)[2]), "+f"((c)[3])         \
                 : "r"((A)[0]), "r"((A)[1]), "r"((A)[2]), "r"((A)[3]),            \
                   "r"(b0v), "r"(b1v))

__device__ __forceinline__ uint32_t splith_pack2(float a, float b, uint32_t& lo_pack) {
    __half ha = __float2half_rn(a), hb = __float2half_rn(b);
    __half la = __float2half_rn(a - __half2float(ha));
    __half lb = __float2half_rn(b - __half2float(hb));
    lo_pack = (uint32_t)__half_as_ushort(la) | ((uint32_t)__half_as_ushort(lb) << 16);
    return (uint32_t)__half_as_ushort(ha) | ((uint32_t)__half_as_ushort(hb) << 16);
}

// ---------------- prologue: coeff -> fp16 (permuted K) + fused bias ----------------
__global__ void prep_kernel(const float* __restrict__ coeff) {
    const int tid = threadIdx.x;
    const int idx = blockIdx.x * 256 + tid;       // edge index [0, 16384)
    const int o = idx >> 7, j = idx & 127;
    float4 cf = reinterpret_cast<const float4*>(coeff)[idx];
    float v[3] = {cf.y, cf.z, cf.w};              // degrees 1..3
    const int cbase = (j >= 64) ? 3 : 0;
#pragma unroll
    for (int pw = 0; pw < 3; ++pw)
        g_Bf[o * KTOT + (cbase + pw) * 64 + (j & 63)] = __float2half_rn(v[pw]);
    float s = cf.x;
#pragma unroll
    for (int off = 16; off; off >>= 1)
        s += __shfl_xor_sync(0xffffffffu, s, off);
    __shared__ float ps[8];
    if ((tid & 31) == 0) ps[tid >> 5] = s;
    __syncthreads();
    if (tid == 0)   g_Bias[o] = ps[0] + ps[1] + ps[2] + ps[3];
    if (tid == 128) g_Bias[o] = ps[4] + ps[5] + ps[6] + ps[7];
}

// ---------------- main kernel ----------------
__global__ void __launch_bounds__(THREADS, 2)
kan_mma(const float* __restrict__ x, float* __restrict__ out) {
    extern __shared__ char smem[];
    const uint32_t sb = smem_u32(smem);
    const int tid  = threadIdx.x;
    const int lane = tid & 31;
    const int wid  = tid >> 5;
    const int b0   = blockIdx.x * MTILE;

    // warp tile coords (16 x 32): 2 m-warps x 4 n-warps
    const int m0 = (wid & 1) * 16;
    const int n0 = (wid >> 1) * 32;

    float acc[4][4];
#pragma unroll
    for (int nj = 0; nj < 4; ++nj)
#pragma unroll
        for (int i = 0; i < 4; ++i) acc[nj][i] = 0.f;

    // ---- B stage loader: 1024 16B loads / 256 threads = 4 each ----
    auto issue_B = [&](int cn, uint32_t tb) {
#pragma unroll
        for (int s = 0; s < 4; ++s) {
            int idx = tid + s * THREADS;          // 0..1023
            int n = idx >> 3, k8 = idx & 7;
            const __half* src = g_Bf + (size_t)n * KTOT + cn * KC + k8 * 8;
            uint32_t dst = tb + swz128((uint32_t)(n * 128 + k8 * 16));
            CP_ASYNC16(sb + dst, src);
        }
    };

    // ---- issue first two B stages, then build the full A tile ----
    issue_B(0, B_BASE);
    CP_COMMIT();
    issue_B(1, B_BASE + B_STAGE_STRIDE);
    CP_COMMIT();

    // Build A: thread handles row sr (0..31), j-octet sq (0..7) of BOTH halves.
    {
        const int sr = tid >> 3;
        const int sq = tid & 7;
        const float4* xr = reinterpret_cast<const float4*>(
            x + (size_t)(b0 + sr) * DIM);
        const uint32_t abase = swz128((uint32_t)(sr * 128 + sq * 16));
#pragma unroll
        for (int h = 0; h < 2; ++h) {
            float4 v0 = xr[h * 16 + sq * 2];
            float4 v1 = xr[h * 16 + sq * 2 + 1];
            float w[8] = {v0.x, v0.y, v0.z, v0.w, v1.x, v1.y, v1.z, v1.w};
#pragma unroll
            for (int pw = 0; pw < 3; ++pw) {
                uint32_t hp[4], lp[4];
#pragma unroll
                for (int i = 0; i < 4; ++i)
                    hp[i] = splith_pack2(w[2 * i], w[2 * i + 1], lp[i]);
                const uint32_t cb = (uint32_t)(h * 3 + pw) * A_CHUNK_STRIDE;
                *reinterpret_cast<uint4*>(smem + cb + abase) =
                    make_uint4(hp[0], hp[1], hp[2], hp[3]);
                *reinterpret_cast<uint4*>(smem + cb + A_LO_OFF + abase) =
                    make_uint4(lp[0], lp[1], lp[2], lp[3]);
                if (pw < 2) {
                    w[0] *= v0.x; w[1] *= v0.y; w[2] *= v0.z; w[3] *= v0.w;
                    w[4] *= v1.x; w[5] *= v1.y; w[6] *= v1.z; w[7] *= v1.w;
                }
            }
        }
    }
    __syncthreads();   // A visible to all warps

    // per-lane ldmatrix base coords
    const uint32_t a_row = (uint32_t)(m0 + (lane & 15));
    const uint32_t a_kb  = (uint32_t)((lane >> 4) * 16);
    const uint32_t b_row = (uint32_t)(n0 + (lane & 7) + ((lane >> 4) << 3));
    const uint32_t b_kb  = (uint32_t)(((lane >> 3) & 1) * 16);

    auto load_frags = [&](uint32_t ab, uint32_t bb, int ks,
                          uint32_t ah[4], uint32_t al[4], uint32_t bf[2][4]) {
        {
            uint32_t off = swz128(a_row * 128 + ks * 32 + a_kb);
            LDSM4(ah, sb + ab + off);
            LDSM4(al, sb + ab + A_LO_OFF + off);
        }
#pragma unroll
        for (int ni = 0; ni < 2; ++ni) {
            uint32_t off = swz128((b_row + ni * 16) * 128 + ks * 32 + b_kb);
            LDSM4(bf[ni], sb + bb + off);
        }
    };
    auto mma_all = [&](uint32_t ah[4], uint32_t al[4], uint32_t bf[2][4]) {
#pragma unroll
        for (int nj = 0; nj < 4; ++nj) {
            const int ni = nj >> 1, br = (nj & 1) * 2;
            MMA_F16(acc[nj], ah, bf[ni][br], bf[ni][br + 1]);
        }
#pragma unroll
        for (int nj = 0; nj < 4; ++nj) {
            const int ni = nj >> 1, br = (nj & 1) * 2;
            MMA_F16(acc[nj], al, bf[ni][br], bf[ni][br + 1]);
        }
    };

#pragma unroll
    for (int c = 0; c < NCHUNK; ++c) {
        if (c < NCHUNK - 1) CP_WAITG(1); else CP_WAITG(0);
        __syncthreads();   // stage c visible; buffer (c+2)%3 free for overwrite

        if (c + 2 < NCHUNK) {
            issue_B(c + 2, B_BASE + (uint32_t)((c + 2) % NSTAGE) * B_STAGE_STRIDE);
            CP_COMMIT();
        }

        const uint32_t ab = (uint32_t)c * A_CHUNK_STRIDE;
        const uint32_t bb = B_BASE + (uint32_t)(c % NSTAGE) * B_STAGE_STRIDE;
        uint32_t ah0[4], al0[4], bf0[2][4];
        uint32_t ah1[4], al1[4], bf1[2][4];
        load_frags(ab, bb, 0, ah0, al0, bf0);
        load_frags(ab, bb, 1, ah1, al1, bf1);
        mma_all(ah0, al0, bf0);
        load_frags(ab, bb, 2, ah0, al0, bf0);
        mma_all(ah1, al1, bf1);
        load_frags(ab, bb, 3, ah1, al1, bf1);
        mma_all(ah0, al0, bf0);
        mma_all(ah1, al1, bf1);
    }

    // ---- epilogue: bias + store ----
    float2 bs[4];
#pragma unroll
    for (int nj = 0; nj < 4; ++nj)
        bs[nj] = *reinterpret_cast<const float2*>(g_Bias + n0 + nj * 8 + 2 * (lane & 3));

    const int r0 = b0 + m0 + (lane >> 2);
#pragma unroll
    for (int nj = 0; nj < 4; ++nj) {
        const int col = n0 + nj * 8 + 2 * (lane & 3);
        float2 v0 = make_float2(acc[nj][0] + bs[nj].x, acc[nj][1] + bs[nj].y);
        float2 v1 = make_float2(acc[nj][2] + bs[nj].x, acc[nj][3] + bs[nj].y);
        *reinterpret_cast<float2*>(out + (size_t)r0 * DIM + col)       = v0;
        *reinterpret_cast<float2*>(out + (size_t)(r0 + 8) * DIM + col) = v1;
    }
}

// ---------------- launch ----------------
extern "C" void kernel_launch(void* const* d_in, const int* in_sizes, int n_in,
                              void* d_out, int out_size) {
    const float* x     = (const float*)d_in[0];   // [8192, 128] fp32
    const float* coeff = (const float*)d_in[1];   // [16384, 4]  fp32
    float* out = (float*)d_out;                   // [8192, 128] fp32

    cudaFuncSetAttribute(kan_mma, cudaFuncAttributeMaxDynamicSharedMemorySize, SMEM_TOTAL);

    prep_kernel<<<64, 256>>>(coeff);
    kan_mma<<<NCTA, THREADS, SMEM_TOTAL>>>(x, out);
}

// round 9
// speedup vs baseline: 1.3434x; 1.0201x over previous
#include <cuda_runtime.h>
#include <cuda_fp16.h>
#include <cstdint>

// Problem dims
#define BATCH    8192
#define DIM      128          // in_dim == out_dim
#define KTOT     384          // permuted K: k = (half*3+pw)*64 + (j&63)
#define KC       64
#define NCHUNK   6
#define MTILE    64           // batch rows per CTA
#define THREADS  512          // 16 warps: 4 (m) x 4 (n)
#define NCTA     (BATCH / MTILE)   // 128 = one full wave

// fp16 coefficients (permuted K order): g_Bf[o*384 + c*64 + (j&63)]
__device__ __half g_Bf[DIM * KTOT];
__device__ float g_Bias[DIM];

// smem layout (192 KB, everything resident, ONE barrier total):
//   A: 6 chunks x { Ah[64][64]f16 8K @ c*16384, Al 8K @ +8192 } = 96 KB @ 0
//   B: 6 chunks x Bf[128][64]f16 16K @ 98304 + c*16384          = 96 KB
#define A_CHUNK_STRIDE 16384u
#define A_LO_OFF       8192u
#define B_BASE         98304u
#define B_CHUNK_STRIDE 16384u
#define SMEM_TOTAL     196608

// ---------------- helpers ----------------
__device__ __forceinline__ uint32_t smem_u32(const void* p) {
    uint32_t a;
    asm("{ .reg .u64 t; cvta.to.shared.u64 t, %1; cvt.u32.u64 %0, t; }" : "=r"(a) : "l"(p));
    return a;
}
__device__ __forceinline__ uint32_t swz128(uint32_t off) { return off ^ ((off >> 3) & 0x70); }

#define CP_ASYNC16(dst_u32, src_ptr)                                              \
    asm volatile("{ .reg .u64 g; cvta.to.global.u64 g, %1;\n"                     \
                 "cp.async.cg.shared.global [%0], [g], 16; }"                     \
                 :: "r"(dst_u32), "l"(src_ptr) : "memory")
#define CP_COMMIT()  asm volatile("cp.async.commit_group;" ::: "memory")
#define CP_WAITG(n)  asm volatile("cp.async.wait_group %0;" :: "n"(n) : "memory")

#define LDSM4(r, addr)                                                            \
    asm volatile("ldmatrix.sync.aligned.m8n8.x4.shared.b16 {%0,%1,%2,%3}, [%4];"  \
                 : "=r"((r)[0]), "=r"((r)[1]), "=r"((r)[2]), "=r"((r)[3])         \
                 : "r"(addr))

#define MMA_F16(c, A, b0v, b1v)                                                   \
    asm volatile("mma.sync.aligned.m16n8k16.row.col.f32.f16.f16.f32 "             \
                 "{%0,%1,%2,%3}, {%4,%5,%6,%7}, {%8,%9}, {%0,%1,%2,%3};"          \
                 : "+f"((c)[0]), "+f"((c)[1]), "+f"((c)[2]), "+f"((c)[3])         \
                 : "r"((A)[0]), "r"((A)[1]), "r"((A)[2]), "r"((A)[3]),            \
                   "r"(b0v), "r"(b1v))

__device__ __forceinline__ uint32_t splith_pack2(float a, float b, uint32_t& lo_pack) {
    __half ha = __float2half_rn(a), hb = __float2half_rn(b);
    __half la = __float2half_rn(a - __half2float(ha));
    __half lb = __float2half_rn(b - __half2float(hb));
    lo_pack = (uint32_t)__half_as_ushort(la) | ((uint32_t)__half_as_ushort(lb) << 16);
    return (uint32_t)__half_as_ushort(ha) | ((uint32_t)__half_as_ushort(hb) << 16);
}

// ---------------- prologue: coeff -> fp16 (permuted K) + fused bias ----------------
__global__ void prep_kernel(const float* __restrict__ coeff) {
    const int tid = threadIdx.x;
    const int idx = blockIdx.x * 256 + tid;       // edge index [0, 16384)
    const int o = idx >> 7, j = idx & 127;
    float4 cf = reinterpret_cast<const float4*>(coeff)[idx];
    float v[3] = {cf.y, cf.z, cf.w};              // degrees 1..3
    const int cbase = (j >= 64) ? 3 : 0;
#pragma unroll
    for (int pw = 0; pw < 3; ++pw)
        g_Bf[o * KTOT + (cbase + pw) * 64 + (j & 63)] = __float2half_rn(v[pw]);
    float s = cf.x;
#pragma unroll
    for (int off = 16; off; off >>= 1)
        s += __shfl_xor_sync(0xffffffffu, s, off);
    __shared__ float ps[8];
    if ((tid & 31) == 0) ps[tid >> 5] = s;
    __syncthreads();
    if (tid == 0)   g_Bias[o] = ps[0] + ps[1] + ps[2] + ps[3];
    if (tid == 128) g_Bias[o] = ps[4] + ps[5] + ps[6] + ps[7];
}

// ---------------- main kernel: barrier-free mainloop ----------------
__global__ void __launch_bounds__(THREADS, 1)
kan_mma(const float* __restrict__ x, float* __restrict__ out) {
    extern __shared__ char smem[];
    const uint32_t sb = smem_u32(smem);
    const int tid  = threadIdx.x;
    const int lane = tid & 31;
    const int wid  = tid >> 5;
    const int b0   = blockIdx.x * MTILE;

    // warp tile (16 x 32): 4 m-warps x 4 n-warps
    const int m0 = (wid & 3) * 16;
    const int n0 = (wid >> 2) * 32;

    // ---- 1) issue ALL B cp.async (96 KB: 6144 16B loads, 12/thread) ----
#pragma unroll
    for (int i = 0; i < 12; ++i) {
        int idx = tid + i * THREADS;              // 0..6143
        int cn = idx >> 10;                       // chunk 0..5
        int n = (idx >> 3) & 127, k8 = idx & 7;
        const __half* src = g_Bf + (size_t)n * KTOT + cn * KC + k8 * 8;
        uint32_t dst = B_BASE + (uint32_t)cn * B_CHUNK_STRIDE
                     + swz128((uint32_t)(n * 128 + k8 * 16));
        CP_ASYNC16(sb + dst, src);
    }
    CP_COMMIT();

    // ---- 2) prefetch bias into registers (overlaps with everything) ----
    float2 bs[4];
#pragma unroll
    for (int nj = 0; nj < 4; ++nj)
        bs[nj] = *reinterpret_cast<const float2*>(g_Bias + n0 + nj * 8 + 2 * (lane & 3));

    // ---- 3) build full A tile (64 rows x 384 K, fp16 hi/lo) ----
    {
        const int sr = tid >> 3;                  // row 0..63
        const int sq = tid & 7;                   // j-octet
        const float4* xr = reinterpret_cast<const float4*>(
            x + (size_t)(b0 + sr) * DIM);
        const uint32_t abase = swz128((uint32_t)(sr * 128 + sq * 16));
#pragma unroll
        for (int h = 0; h < 2; ++h) {
            float4 v0 = xr[h * 16 + sq * 2];
            float4 v1 = xr[h * 16 + sq * 2 + 1];
            float w[8] = {v0.x, v0.y, v0.z, v0.w, v1.x, v1.y, v1.z, v1.w};
#pragma unroll
            for (int pw = 0; pw < 3; ++pw) {
                uint32_t hp[4], lp[4];
#pragma unroll
                for (int i = 0; i < 4; ++i)
                    hp[i] = splith_pack2(w[2 * i], w[2 * i + 1], lp[i]);
                const uint32_t cb = (uint32_t)(h * 3 + pw) * A_CHUNK_STRIDE;
                *reinterpret_cast<uint4*>(smem + cb + abase) =
                    make_uint4(hp[0], hp[1], hp[2], hp[3]);
                *reinterpret_cast<uint4*>(smem + cb + A_LO_OFF + abase) =
                    make_uint4(lp[0], lp[1], lp[2], lp[3]);
                if (pw < 2) {
                    w[0] *= v0.x; w[1] *= v0.y; w[2] *= v0.z; w[3] *= v0.w;
                    w[4] *= v1.x; w[5] *= v1.y; w[6] *= v1.z; w[7] *= v1.w;
                }
            }
        }
    }

    // ---- 4) THE single synchronization point of the whole kernel ----
    CP_WAITG(0);
    __syncthreads();

    // ---- 5) barrier-free mainloop: 24 k16-steps per warp ----
    float acc[4][4];
#pragma unroll
    for (int nj = 0; nj < 4; ++nj)
#pragma unroll
        for (int i = 0; i < 4; ++i) acc[nj][i] = 0.f;

    const uint32_t a_row = (uint32_t)(m0 + (lane & 15));
    const uint32_t a_kb  = (uint32_t)((lane >> 4) * 16);
    const uint32_t b_row = (uint32_t)(n0 + (lane & 7) + ((lane >> 4) << 3));
    const uint32_t b_kb  = (uint32_t)(((lane >> 3) & 1) * 16);

    auto load_frags = [&](uint32_t ab, uint32_t bb, int ks,
                          uint32_t ah[4], uint32_t al[4], uint32_t bf[2][4]) {
        {
            uint32_t off = swz128(a_row * 128 + ks * 32 + a_kb);
            LDSM4(ah, sb + ab + off);
            LDSM4(al, sb + ab + A_LO_OFF + off);
        }
#pragma unroll
        for (int ni = 0; ni < 2; ++ni) {
            uint32_t off = swz128((b_row + ni * 16) * 128 + ks * 32 + b_kb);
            LDSM4(bf[ni], sb + bb + off);
        }
    };
    auto mma_all = [&](uint32_t ah[4], uint32_t al[4], uint32_t bf[2][4]) {
#pragma unroll
        for (int nj = 0; nj < 4; ++nj) {
            const int ni = nj >> 1, br = (nj & 1) * 2;
            MMA_F16(acc[nj], ah, bf[ni][br], bf[ni][br + 1]);
        }
#pragma unroll
        for (int nj = 0; nj < 4; ++nj) {
            const int ni = nj >> 1, br = (nj & 1) * 2;
            MMA_F16(acc[nj], al, bf[ni][br], bf[ni][br + 1]);
        }
    };

#pragma unroll
    for (int c = 0; c < NCHUNK; ++c) {
        const uint32_t ab = (uint32_t)c * A_CHUNK_STRIDE;
        const uint32_t bb = B_BASE + (uint32_t)c * B_CHUNK_STRIDE;
        uint32_t ah0[4], al0[4], bf0[2][4];
        uint32_t ah1[4], al1[4], bf1[2][4];
        load_frags(ab, bb, 0, ah0, al0, bf0);
        load_frags(ab, bb, 1, ah1, al1, bf1);
        mma_all(ah0, al0, bf0);
        load_frags(ab, bb, 2, ah0, al0, bf0);
        mma_all(ah1, al1, bf1);
        load_frags(ab, bb, 3, ah1, al1, bf1);
        mma_all(ah0, al0, bf0);
        mma_all(ah1, al1, bf1);
    }

    // ---- 6) epilogue: bias + store (no sync needed) ----
    const int r0 = b0 + m0 + (lane >> 2);
#pragma unroll
    for (int nj = 0; nj < 4; ++nj) {
        const int col = n0 + nj * 8 + 2 * (lane & 3);
        float2 v0 = make_float2(acc[nj][0] + bs[nj].x, acc[nj][1] + bs[nj].y);
        float2 v1 = make_float2(acc[nj][2] + bs[nj].x, acc[nj][3] + bs[nj].y);
        *reinterpret_cast<float2*>(out + (size_t)r0 * DIM + col)       = v0;
        *reinterpret_cast<float2*>(out + (size_t)(r0 + 8) * DIM + col) = v1;
    }
}

// ---------------- launch ----------------
extern "C" void kernel_launch(void* const* d_in, const int* in_sizes, int n_in,
                              void* d_out, int out_size) {
    const float* x     = (const float*)d_in[0];   // [8192, 128] fp32
    const float* coeff = (const float*)d_in[1];   // [16384, 4]  fp32
    float* out = (float*)d_out;                   // [8192, 128] fp32

    cudaFuncSetAttribute(kan_mma, cudaFuncAttributeMaxDynamicSharedMemorySize, SMEM_TOTAL);

    prep_kernel<<<64, 256>>>(coeff);
    kan_mma<<<NCTA, THREADS, SMEM_TOTAL>>>(x, out);
}